// round 1
// baseline (speedup 1.0000x reference)
#include <cuda_runtime.h>
#include <math.h>

#define BB 32
#define SS 512
#define HH 768
#define MC 128
#define EPSF 1e-8f

// ---------------- scratch (static device memory; no allocs) ----------------
__device__ float g_keyconf[BB*SS];
__device__ float g_valconf[BB*SS];
__device__ int   g_kidx[BB*MC];
__device__ int   g_vidx[BB*MC];
__device__ float g_kbox[BB*MC*4];
__device__ float g_vbox[BB*MC*4];
__device__ float g_keyreps[BB*MC*HH];
__device__ float g_valreps[BB*MC*HH];
__device__ float g_tmp[BB*MC*HH];
__device__ float g_biaf[BB*MC*MC];

// ---------------- 1) softmax + argmax + mask ----------------
__global__ void conf_kernel(const float* __restrict__ logits,
                            const int* __restrict__ mask) {
    int t = blockIdx.x * blockDim.x + threadIdx.x;
    if (t >= BB * SS) return;
    float l0 = logits[3*t+0], l1 = logits[3*t+1], l2 = logits[3*t+2];
    int pred = 0; float best = l0;
    if (l1 > best) { pred = 1; best = l1; }
    if (l2 > best) { pred = 2; best = l2; }
    float e0 = expf(l0 - best), e1 = expf(l1 - best), e2 = expf(l2 - best);
    float inv = 1.0f / (e0 + e1 + e2);
    bool valid = (mask[t] == 1);
    float ninf = -INFINITY;
    g_keyconf[t] = (pred == 1 && valid) ? e1 * inv : ninf;
    g_valconf[t] = (pred == 2 && valid) ? e2 * inv : ninf;
}

// ---------------- 2) exact top-128 of 512 via bitonic sort ----------------
// Comparator matches jax.lax.top_k: descending value, ascending index on ties.
__global__ void topk_kernel(const float* __restrict__ bboxes,
                            float* __restrict__ out) {
    int b = blockIdx.x;
    int which = blockIdx.y;   // 0 = key, 1 = val
    const float* conf = (which == 0) ? g_keyconf : g_valconf;
    __shared__ float sc[512];
    __shared__ int   si[512];
    int tid = threadIdx.x;
    sc[tid] = conf[b * SS + tid];
    si[tid] = tid;

    for (int k = 2; k <= 512; k <<= 1) {
        for (int j = k >> 1; j > 0; j >>= 1) {
            __syncthreads();
            int ixj = tid ^ j;
            if (ixj > tid) {
                float c1 = sc[tid], c2 = sc[ixj];
                int   i1 = si[tid], i2 = si[ixj];
                // "better" = should come first
                bool b2 = (c2 > c1) || (c2 == c1 && i2 < i1); // ixj better than tid
                bool doswap = ((tid & k) == 0) ? b2 : !b2;
                if (doswap) {
                    sc[tid] = c2; si[tid] = i2;
                    sc[ixj] = c1; si[ixj] = i1;
                }
            }
        }
    }
    __syncthreads();

    if (tid < MC) {
        int   idx = si[tid];
        float cf  = sc[tid];
        int*   gi = (which == 0) ? g_kidx : g_vidx;
        float* gb = (which == 0) ? g_kbox : g_vbox;
        gi[b * MC + tid] = idx;
        const float* src = bboxes + ((long long)b * SS + idx) * 4;
        float* dst = gb + (b * MC + tid) * 4;
        dst[0] = src[0]; dst[1] = src[1]; dst[2] = src[2]; dst[3] = src[3];
        // output tail: [scores | key_valid | val_valid | kidx | vidx] (float32)
        long long base = (long long)BB * MC * MC;            // 524288
        float vf = (cf != -INFINITY) ? 1.0f : 0.0f;
        out[base + (long long)which * (BB * MC) + b * MC + tid] = vf;
        out[base + 2LL * (BB * MC) + (long long)which * (BB * MC) + b * MC + tid] = (float)idx;
    }
}

// ---------------- 3) M=4096 N=768 K=768 SGEMM (optionally gathered A) ------
// mode 0: A = seq gathered via g_kidx, C = g_keyreps, bias = bk
// mode 1: A = seq gathered via g_vidx, C = g_valreps, bias = bv
// mode 2: A = g_keyreps (direct),      C = g_tmp,     bias = none
__global__ void gemm_kernel(int mode, const float* __restrict__ seq,
                            const float* __restrict__ Bm,
                            const float* __restrict__ bias) {
    __shared__ float As[16][65];
    __shared__ float Bs[16][64];
    __shared__ long long rowbase[64];

    int tx = threadIdx.x, ty = threadIdx.y;
    int tid = ty * 16 + tx;
    int m0 = blockIdx.y * 64;
    int c0 = blockIdx.x * 64;

    const float* A;
    float* C;
    const int* gidx = nullptr;
    if (mode == 0)      { A = seq;       C = g_keyreps; gidx = g_kidx; }
    else if (mode == 1) { A = seq;       C = g_valreps; gidx = g_vidx; }
    else                { A = g_keyreps; C = g_tmp; }

    if (tid < 64) {
        int m = m0 + tid;
        long long base;
        if (gidx) {
            int b = m >> 7;
            base = ((long long)b * SS + gidx[m]) * HH;
        } else {
            base = (long long)m * HH;
        }
        rowbase[tid] = base;
    }

    float acc[4][4];
    #pragma unroll
    for (int i = 0; i < 4; i++)
        #pragma unroll
        for (int j = 0; j < 4; j++) acc[i][j] = 0.0f;

    for (int k0 = 0; k0 < HH; k0 += 16) {
        __syncthreads();
        {   // A tile: 64 rows x 16 k, float4 per thread
            int r  = tid >> 2;
            int kk = (tid & 3) * 4;
            const float* ap = A + rowbase[r] + k0 + kk;
            float4 v = *(const float4*)ap;
            As[kk+0][r] = v.x; As[kk+1][r] = v.y;
            As[kk+2][r] = v.z; As[kk+3][r] = v.w;
        }
        #pragma unroll
        for (int e = 0; e < 4; e++) { // B tile: 16 k x 64 cols
            int idx = tid + e * 256;
            int kk = idx >> 6, c = idx & 63;
            Bs[kk][c] = Bm[(k0 + kk) * HH + c0 + c];
        }
        __syncthreads();
        #pragma unroll
        for (int kk = 0; kk < 16; kk++) {
            float a[4], bv[4];
            #pragma unroll
            for (int i = 0; i < 4; i++) a[i] = As[kk][ty * 4 + i];
            #pragma unroll
            for (int j = 0; j < 4; j++) bv[j] = Bs[kk][tx * 4 + j];
            #pragma unroll
            for (int i = 0; i < 4; i++)
                #pragma unroll
                for (int j = 0; j < 4; j++)
                    acc[i][j] = fmaf(a[i], bv[j], acc[i][j]);
        }
    }

    #pragma unroll
    for (int i = 0; i < 4; i++) {
        int r = m0 + ty * 4 + i;
        #pragma unroll
        for (int j = 0; j < 4; j++) {
            int c = c0 + tx * 4 + j;
            float v = acc[i][j];
            if (bias) v += bias[c];
            C[(long long)r * HH + c] = v;
        }
    }
}

// ---------------- 4) biaffine: C[b,i,j] = dot(tmp[b,i,:], val[b,j,:]) + bbil
__global__ void biaf_kernel(const float* __restrict__ bbilp) {
    int bb = blockIdx.z;
    int m0 = blockIdx.y * 64;
    int n0 = blockIdx.x * 64;
    __shared__ float As[16][65];
    __shared__ float Bs[16][65];

    int tx = threadIdx.x, ty = threadIdx.y;
    int tid = ty * 16 + tx;

    const float* A = g_tmp     + (long long)bb * MC * HH;
    const float* V = g_valreps + (long long)bb * MC * HH;

    float acc[4][4];
    #pragma unroll
    for (int i = 0; i < 4; i++)
        #pragma unroll
        for (int j = 0; j < 4; j++) acc[i][j] = 0.0f;

    for (int k0 = 0; k0 < HH; k0 += 16) {
        __syncthreads();
        {
            int r  = tid >> 2;
            int kk = (tid & 3) * 4;
            float4 va = *(const float4*)(A + (long long)(m0 + r) * HH + k0 + kk);
            As[kk+0][r] = va.x; As[kk+1][r] = va.y;
            As[kk+2][r] = va.z; As[kk+3][r] = va.w;
            float4 vb = *(const float4*)(V + (long long)(n0 + r) * HH + k0 + kk);
            Bs[kk+0][r] = vb.x; Bs[kk+1][r] = vb.y;
            Bs[kk+2][r] = vb.z; Bs[kk+3][r] = vb.w;
        }
        __syncthreads();
        #pragma unroll
        for (int kk = 0; kk < 16; kk++) {
            float a[4], bv[4];
            #pragma unroll
            for (int i = 0; i < 4; i++) a[i] = As[kk][ty * 4 + i];
            #pragma unroll
            for (int j = 0; j < 4; j++) bv[j] = Bs[kk][tx * 4 + j];
            #pragma unroll
            for (int i = 0; i < 4; i++)
                #pragma unroll
                for (int j = 0; j < 4; j++)
                    acc[i][j] = fmaf(a[i], bv[j], acc[i][j]);
        }
    }

    float bbil = *bbilp;
    #pragma unroll
    for (int i = 0; i < 4; i++) {
        int r = m0 + ty * 4 + i;
        #pragma unroll
        for (int j = 0; j < 4; j++) {
            int c = n0 + tx * 4 + j;
            g_biaf[(long long)bb * (MC * MC) + r * MC + c] = acc[i][j] + bbil;
        }
    }
}

// ---------------- 5) spatial features + MLP + final scores ----------------
__global__ void pair_kernel(float* __restrict__ out,
                            const float* __restrict__ Ws1, const float* __restrict__ bs1,
                            const float* __restrict__ Ws2, const float* __restrict__ bs2,
                            const float* __restrict__ Wf1, const float* __restrict__ bf1,
                            const float* __restrict__ Wf2, const float* __restrict__ bf2) {
    __shared__ float sW1[8 * 64], sb1[64];
    __shared__ float sW2[64 * 32], sb2[32];
    __shared__ float sF1[33 * 16], sb3[16], sF2[16];
    __shared__ float sbf2;
    __shared__ float kb[4];

    int i = blockIdx.x;
    int b = blockIdx.y;
    int j = threadIdx.x;

    for (int t = j; t < 512;  t += 128) sW1[t] = Ws1[t];
    for (int t = j; t < 2048; t += 128) sW2[t] = Ws2[t];
    for (int t = j; t < 528;  t += 128) sF1[t] = Wf1[t];
    if (j < 64) sb1[j] = bs1[j];
    if (j < 32) sb2[j] = bs2[j];
    if (j < 16) { sb3[j] = bf1[j]; sF2[j] = Wf2[j]; }
    if (j == 0) sbf2 = bf2[0];
    if (j < 4)  kb[j] = g_kbox[(b * MC + i) * 4 + j];
    __syncthreads();

    float vx1 = g_vbox[(b * MC + j) * 4 + 0];
    float vy1 = g_vbox[(b * MC + j) * 4 + 1];
    float vx2 = g_vbox[(b * MC + j) * 4 + 2];
    float vy2 = g_vbox[(b * MC + j) * 4 + 3];
    float kx1 = kb[0], ky1 = kb[1], kx2 = kb[2], ky2 = kb[3];

    float kcx = (kx1 + kx2) * 0.5f, kcy = (ky1 + ky2) * 0.5f;
    float vcx = (vx1 + vx2) * 0.5f, vcy = (vy1 + vy2) * 0.5f;
    float dx = vcx - kcx, dy = vcy - kcy;
    float dist  = sqrtf(dx * dx + dy * dy + EPSF);
    float angle = atan2f(dy, dx);
    float kh = ky2 - ky1, kw = kx2 - kx1;
    float vh = vy2 - vy1, vw = vx2 - vx1;
    float h_ov = fmaxf(fminf(ky2, vy2) - fmaxf(ky1, vy1), 0.0f);
    float h_align = h_ov / (fminf(kh, vh) + EPSF);
    float v_ov = fmaxf(fminf(kx2, vx2) - fmaxf(kx1, vx1), 0.0f);
    float v_align = v_ov / (fminf(kw, vw) + EPSF);
    float area_ratio   = (vh * vw) / (kh * kw + EPSF);
    float aspect_ratio = (vw / (vh + EPSF)) / (kw / (kh + EPSF));

    float sf[8] = { dx, dy, dist, angle, h_align, v_align, area_ratio, aspect_ratio };

    float h2[32];
    #pragma unroll
    for (int t = 0; t < 32; t++) h2[t] = sb2[t];

    for (int u = 0; u < 64; u++) {
        float h = sb1[u];
        #pragma unroll
        for (int f = 0; f < 8; f++) h = fmaf(sf[f], sW1[f * 64 + u], h);
        h = fmaxf(h, 0.0f);
        #pragma unroll
        for (int t = 0; t < 32; t++) h2[t] = fmaf(h, sW2[u * 32 + t], h2[t]);
    }

    float biafv = g_biaf[(long long)b * (MC * MC) + i * MC + j];

    float f1[16];
    #pragma unroll
    for (int t = 0; t < 16; t++) f1[t] = fmaf(biafv, sF1[t], sb3[t]); // combined[0]
    for (int t2 = 0; t2 < 32; t2++) {
        float hv = h2[t2];
        #pragma unroll
        for (int t = 0; t < 16; t++) f1[t] = fmaf(hv, sF1[(t2 + 1) * 16 + t], f1[t]);
    }

    float score = sbf2;
    #pragma unroll
    for (int t = 0; t < 16; t++) score = fmaf(fmaxf(f1[t], 0.0f), sF2[t], score);

    out[(long long)b * (MC * MC) + i * MC + j] = score;
}

// ---------------- launch ----------------
extern "C" void kernel_launch(void* const* d_in, const int* in_sizes, int n_in,
                              void* d_out, int out_size) {
    (void)in_sizes; (void)n_in; (void)out_size;
    const float* seq    = (const float*)d_in[0];
    const float* logits = (const float*)d_in[1];
    const float* bboxes = (const float*)d_in[2];
    const int*   mask   = (const int*)  d_in[3];
    const float* Wk  = (const float*)d_in[4];
    const float* bk  = (const float*)d_in[5];
    const float* Wv  = (const float*)d_in[6];
    const float* bv  = (const float*)d_in[7];
    const float* Wbil= (const float*)d_in[8];
    const float* bbil= (const float*)d_in[9];
    const float* Ws1 = (const float*)d_in[10];
    const float* bs1 = (const float*)d_in[11];
    const float* Ws2 = (const float*)d_in[12];
    const float* bs2 = (const float*)d_in[13];
    const float* Wf1 = (const float*)d_in[14];
    const float* bf1 = (const float*)d_in[15];
    const float* Wf2 = (const float*)d_in[16];
    const float* bf2 = (const float*)d_in[17];
    float* out = (float*)d_out;

    conf_kernel<<<(BB * SS + 255) / 256, 256>>>(logits, mask);
    topk_kernel<<<dim3(BB, 2), 512>>>(bboxes, out);

    dim3 tgemm(16, 16);
    dim3 ggemm(HH / 64, (BB * MC) / 64);    // 12 x 64
    gemm_kernel<<<ggemm, tgemm>>>(0, seq, Wk, bk);
    gemm_kernel<<<ggemm, tgemm>>>(1, seq, Wv, bv);
    gemm_kernel<<<ggemm, tgemm>>>(2, seq, Wbil, nullptr);

    biaf_kernel<<<dim3(2, 2, BB), tgemm>>>(bbil);

    pair_kernel<<<dim3(MC, BB), 128>>>(out, Ws1, bs1, Ws2, bs2, Wf1, bf1, Wf2, bf2);
}

// round 2
// speedup vs baseline: 1.2163x; 1.2163x over previous
#include <cuda_runtime.h>
#include <math.h>

#define BB 32
#define SS 512
#define HH 768
#define MC 128
#define EPSF 1e-8f
#define TK 16

// ---------------- scratch (static device memory; no allocs) ----------------
__device__ float g_keyconf[BB*SS];
__device__ float g_valconf[BB*SS];
__device__ int   g_kidx[BB*MC];
__device__ int   g_vidx[BB*MC];
__device__ float g_kbox[BB*MC*4];
__device__ float g_vbox[BB*MC*4];
__device__ float g_valreps[BB*MC*HH];
__device__ float g_tmp[BB*MC*HH];
__device__ float g_biaf[BB*MC*MC];
__device__ float g_Wc[HH*HH];
__device__ float g_bc[HH];

// ---------------- 1) softmax + argmax + mask ----------------
__global__ void conf_kernel(const float* __restrict__ logits,
                            const int* __restrict__ mask) {
    int t = blockIdx.x * blockDim.x + threadIdx.x;
    if (t >= BB * SS) return;
    float l0 = logits[3*t+0], l1 = logits[3*t+1], l2 = logits[3*t+2];
    int pred = 0; float best = l0;
    if (l1 > best) { pred = 1; best = l1; }
    if (l2 > best) { pred = 2; best = l2; }
    float e0 = expf(l0 - best), e1 = expf(l1 - best), e2 = expf(l2 - best);
    float inv = 1.0f / (e0 + e1 + e2);
    bool valid = (mask[t] == 1);
    float ninf = -INFINITY;
    g_keyconf[t] = (pred == 1 && valid) ? e1 * inv : ninf;
    g_valconf[t] = (pred == 2 && valid) ? e2 * inv : ninf;
}

// ---------------- 2) exact top-128 of 512 via bitonic sort ----------------
__global__ void topk_kernel(const float* __restrict__ bboxes,
                            float* __restrict__ out) {
    int b = blockIdx.x;
    int which = blockIdx.y;   // 0 = key, 1 = val
    const float* conf = (which == 0) ? g_keyconf : g_valconf;
    __shared__ float sc[512];
    __shared__ int   si[512];
    int tid = threadIdx.x;
    sc[tid] = conf[b * SS + tid];
    si[tid] = tid;

    for (int k = 2; k <= 512; k <<= 1) {
        for (int j = k >> 1; j > 0; j >>= 1) {
            __syncthreads();
            int ixj = tid ^ j;
            if (ixj > tid) {
                float c1 = sc[tid], c2 = sc[ixj];
                int   i1 = si[tid], i2 = si[ixj];
                bool b2 = (c2 > c1) || (c2 == c1 && i2 < i1);
                bool doswap = ((tid & k) == 0) ? b2 : !b2;
                if (doswap) {
                    sc[tid] = c2; si[tid] = i2;
                    sc[ixj] = c1; si[ixj] = i1;
                }
            }
        }
    }
    __syncthreads();

    if (tid < MC) {
        int   idx = si[tid];
        float cf  = sc[tid];
        int*   gi = (which == 0) ? g_kidx : g_vidx;
        float* gb = (which == 0) ? g_kbox : g_vbox;
        gi[b * MC + tid] = idx;
        const float* src = bboxes + ((long long)b * SS + idx) * 4;
        float* dst = gb + (b * MC + tid) * 4;
        dst[0] = src[0]; dst[1] = src[1]; dst[2] = src[2]; dst[3] = src[3];
        long long base = (long long)BB * MC * MC;            // 524288
        float vf = (cf != -INFINITY) ? 1.0f : 0.0f;
        out[base + (long long)which * (BB * MC) + b * MC + tid] = vf;
        out[base + 2LL * (BB * MC) + (long long)which * (BB * MC) + b * MC + tid] = (float)idx;
    }
}

// ---------------- bc[j] = sum_h bk[h] * Wbil[h,j] ----------------
__global__ void bc_kernel(const float* __restrict__ bk,
                          const float* __restrict__ Wbil) {
    int j = blockIdx.x * 128 + threadIdx.x;
    float s = 0.0f;
    for (int h = 0; h < HH; h++) s = fmaf(bk[h], Wbil[h * HH + j], s);
    g_bc[j] = s;
}

// ---------------- 3) 128x128-tile SGEMM, 8x8/thread, double-buffered ------
// blockIdx.z selects job slot. C[m, c] = A[row(m), :] @ B[:, c] + bias[c]
__global__ __launch_bounds__(256)
void sgemm128(const float* __restrict__ A0, const float* __restrict__ B0,
              const float* __restrict__ bias0, float* __restrict__ C0, const int* __restrict__ g0,
              const float* __restrict__ A1, const float* __restrict__ B1,
              const float* __restrict__ bias1, float* __restrict__ C1, const int* __restrict__ g1) {
    __shared__ float As[2][TK][132];
    __shared__ float Bs[2][TK][128];
    __shared__ long long rowbase[128];

    const float* A; const float* Bm; const float* bias; float* C; const int* gidx;
    if (blockIdx.z == 0) { A = A0; Bm = B0; bias = bias0; C = C0; gidx = g0; }
    else                 { A = A1; Bm = B1; bias = bias1; C = C1; gidx = g1; }

    int tid = threadIdx.x;
    int tx = tid & 15, ty = tid >> 4;
    int m0 = blockIdx.y * 128, c0 = blockIdx.x * 128;

    if (tid < 128) {
        int m = m0 + tid;
        long long base;
        if (gidx) { int b = m >> 7; base = ((long long)b * SS + gidx[m]) * HH; }
        else      { base = (long long)m * HH; }
        rowbase[tid] = base;
    }
    __syncthreads();

    // load assignments
    int ar0 = tid >> 2;           // 0..63
    int ak0 = (tid & 3) * 4;      // 0,4,8,12
    int ar1 = ar0 + 64;
    int bk0 = tid >> 5;           // 0..7
    int bc0 = (tid & 31) * 4;     // 0..124
    int bk1 = bk0 + 8;

    long long ra0 = rowbase[ar0];
    long long ra1 = rowbase[ar1];

    float4 a0v, a1v, b0v, b1v;

#define LOAD_REGS(K0) do { \
        a0v = *(const float4*)(A + ra0 + (K0) + ak0); \
        a1v = *(const float4*)(A + ra1 + (K0) + ak0); \
        b0v = *(const float4*)(Bm + (long long)((K0) + bk0) * HH + c0 + bc0); \
        b1v = *(const float4*)(Bm + (long long)((K0) + bk1) * HH + c0 + bc0); \
    } while (0)

#define STORE_SMEM(BUF) do { \
        As[BUF][ak0+0][ar0] = a0v.x; As[BUF][ak0+1][ar0] = a0v.y; \
        As[BUF][ak0+2][ar0] = a0v.z; As[BUF][ak0+3][ar0] = a0v.w; \
        As[BUF][ak0+0][ar1] = a1v.x; As[BUF][ak0+1][ar1] = a1v.y; \
        As[BUF][ak0+2][ar1] = a1v.z; As[BUF][ak0+3][ar1] = a1v.w; \
        *(float4*)&Bs[BUF][bk0][bc0] = b0v; \
        *(float4*)&Bs[BUF][bk1][bc0] = b1v; \
    } while (0)

    float acc[8][8];
    #pragma unroll
    for (int i = 0; i < 8; i++)
        #pragma unroll
        for (int j = 0; j < 8; j++) acc[i][j] = 0.0f;

    LOAD_REGS(0);
    STORE_SMEM(0);
    __syncthreads();

    const int NT = HH / TK;   // 48
    for (int kt = 0; kt < NT; kt++) {
        int cur = kt & 1;
        if (kt + 1 < NT) LOAD_REGS((kt + 1) * TK);
        #pragma unroll
        for (int kk = 0; kk < TK; kk++) {
            float a[8], b[8];
            *(float4*)(a)     = *(const float4*)&As[cur][kk][ty * 8];
            *(float4*)(a + 4) = *(const float4*)&As[cur][kk][ty * 8 + 4];
            *(float4*)(b)     = *(const float4*)&Bs[cur][kk][tx * 8];
            *(float4*)(b + 4) = *(const float4*)&Bs[cur][kk][tx * 8 + 4];
            #pragma unroll
            for (int i = 0; i < 8; i++)
                #pragma unroll
                for (int j = 0; j < 8; j++)
                    acc[i][j] = fmaf(a[i], b[j], acc[i][j]);
        }
        if (kt + 1 < NT) {
            STORE_SMEM(cur ^ 1);
            __syncthreads();
        }
    }

    float bv8[8];
    #pragma unroll
    for (int j = 0; j < 8; j++) bv8[j] = bias ? bias[c0 + tx * 8 + j] : 0.0f;

    #pragma unroll
    for (int i = 0; i < 8; i++) {
        int r = m0 + ty * 8 + i;
        float4 v0, v1;
        v0.x = acc[i][0] + bv8[0]; v0.y = acc[i][1] + bv8[1];
        v0.z = acc[i][2] + bv8[2]; v0.w = acc[i][3] + bv8[3];
        v1.x = acc[i][4] + bv8[4]; v1.y = acc[i][5] + bv8[5];
        v1.z = acc[i][6] + bv8[6]; v1.w = acc[i][7] + bv8[7];
        *(float4*)&C[(long long)r * HH + c0 + tx * 8]     = v0;
        *(float4*)&C[(long long)r * HH + c0 + tx * 8 + 4] = v1;
    }
#undef LOAD_REGS
#undef STORE_SMEM
}

// ---------------- 4) biaffine: C[b,i,j] = dot(tmp[b,i,:], val[b,j,:]) + bbil
__global__ void biaf_kernel(const float* __restrict__ bbilp) {
    int bb = blockIdx.z;
    int m0 = blockIdx.y * 64;
    int n0 = blockIdx.x * 64;
    __shared__ float As[16][65];
    __shared__ float Bs[16][65];

    int tx = threadIdx.x, ty = threadIdx.y;
    int tid = ty * 16 + tx;

    const float* A = g_tmp     + (long long)bb * MC * HH;
    const float* V = g_valreps + (long long)bb * MC * HH;

    float acc[4][4];
    #pragma unroll
    for (int i = 0; i < 4; i++)
        #pragma unroll
        for (int j = 0; j < 4; j++) acc[i][j] = 0.0f;

    for (int k0 = 0; k0 < HH; k0 += 16) {
        __syncthreads();
        {
            int r  = tid >> 2;
            int kk = (tid & 3) * 4;
            float4 va = *(const float4*)(A + (long long)(m0 + r) * HH + k0 + kk);
            As[kk+0][r] = va.x; As[kk+1][r] = va.y;
            As[kk+2][r] = va.z; As[kk+3][r] = va.w;
            float4 vb = *(const float4*)(V + (long long)(n0 + r) * HH + k0 + kk);
            Bs[kk+0][r] = vb.x; Bs[kk+1][r] = vb.y;
            Bs[kk+2][r] = vb.z; Bs[kk+3][r] = vb.w;
        }
        __syncthreads();
        #pragma unroll
        for (int kk = 0; kk < 16; kk++) {
            float a[4], bv[4];
            #pragma unroll
            for (int i = 0; i < 4; i++) a[i] = As[kk][ty * 4 + i];
            #pragma unroll
            for (int j = 0; j < 4; j++) bv[j] = Bs[kk][tx * 4 + j];
            #pragma unroll
            for (int i = 0; i < 4; i++)
                #pragma unroll
                for (int j = 0; j < 4; j++)
                    acc[i][j] = fmaf(a[i], bv[j], acc[i][j]);
        }
    }

    float bbil = *bbilp;
    #pragma unroll
    for (int i = 0; i < 4; i++) {
        int r = m0 + ty * 4 + i;
        #pragma unroll
        for (int j = 0; j < 4; j++) {
            int c = n0 + tx * 4 + j;
            g_biaf[(long long)bb * (MC * MC) + r * MC + c] = acc[i][j] + bbil;
        }
    }
}

// ---------------- 5) spatial features + MLP + final scores ----------------
__global__ void pair_kernel(float* __restrict__ out,
                            const float* __restrict__ Ws1, const float* __restrict__ bs1,
                            const float* __restrict__ Ws2, const float* __restrict__ bs2,
                            const float* __restrict__ Wf1, const float* __restrict__ bf1,
                            const float* __restrict__ Wf2, const float* __restrict__ bf2) {
    __shared__ float sW1[8 * 64], sb1[64];
    __shared__ float sW2[64 * 32], sb2[32];
    __shared__ float sF1[33 * 16], sb3[16], sF2[16];
    __shared__ float sbf2;
    __shared__ float kb[4];

    int i = blockIdx.x;
    int b = blockIdx.y;
    int j = threadIdx.x;

    for (int t = j; t < 512;  t += 128) sW1[t] = Ws1[t];
    for (int t = j; t < 2048; t += 128) sW2[t] = Ws2[t];
    for (int t = j; t < 528;  t += 128) sF1[t] = Wf1[t];
    if (j < 64) sb1[j] = bs1[j];
    if (j < 32) sb2[j] = bs2[j];
    if (j < 16) { sb3[j] = bf1[j]; sF2[j] = Wf2[j]; }
    if (j == 0) sbf2 = bf2[0];
    if (j < 4)  kb[j] = g_kbox[(b * MC + i) * 4 + j];
    __syncthreads();

    float vx1 = g_vbox[(b * MC + j) * 4 + 0];
    float vy1 = g_vbox[(b * MC + j) * 4 + 1];
    float vx2 = g_vbox[(b * MC + j) * 4 + 2];
    float vy2 = g_vbox[(b * MC + j) * 4 + 3];
    float kx1 = kb[0], ky1 = kb[1], kx2 = kb[2], ky2 = kb[3];

    float kcx = (kx1 + kx2) * 0.5f, kcy = (ky1 + ky2) * 0.5f;
    float vcx = (vx1 + vx2) * 0.5f, vcy = (vy1 + vy2) * 0.5f;
    float dx = vcx - kcx, dy = vcy - kcy;
    float dist  = sqrtf(dx * dx + dy * dy + EPSF);
    float angle = atan2f(dy, dx);
    float kh = ky2 - ky1, kw = kx2 - kx1;
    float vh = vy2 - vy1, vw = vx2 - vx1;
    float h_ov = fmaxf(fminf(ky2, vy2) - fmaxf(ky1, vy1), 0.0f);
    float h_align = h_ov / (fminf(kh, vh) + EPSF);
    float v_ov = fmaxf(fminf(kx2, vx2) - fmaxf(kx1, vx1), 0.0f);
    float v_align = v_ov / (fminf(kw, vw) + EPSF);
    float area_ratio   = (vh * vw) / (kh * kw + EPSF);
    float aspect_ratio = (vw / (vh + EPSF)) / (kw / (kh + EPSF));

    float sf[8] = { dx, dy, dist, angle, h_align, v_align, area_ratio, aspect_ratio };

    float h2[32];
    #pragma unroll
    for (int t = 0; t < 32; t++) h2[t] = sb2[t];

    for (int u = 0; u < 64; u++) {
        float h = sb1[u];
        #pragma unroll
        for (int f = 0; f < 8; f++) h = fmaf(sf[f], sW1[f * 64 + u], h);
        h = fmaxf(h, 0.0f);
        #pragma unroll
        for (int t = 0; t < 32; t++) h2[t] = fmaf(h, sW2[u * 32 + t], h2[t]);
    }

    float biafv = g_biaf[(long long)b * (MC * MC) + i * MC + j];

    float f1[16];
    #pragma unroll
    for (int t = 0; t < 16; t++) f1[t] = fmaf(biafv, sF1[t], sb3[t]);
    for (int t2 = 0; t2 < 32; t2++) {
        float hv = h2[t2];
        #pragma unroll
        for (int t = 0; t < 16; t++) f1[t] = fmaf(hv, sF1[(t2 + 1) * 16 + t], f1[t]);
    }

    float score = sbf2;
    #pragma unroll
    for (int t = 0; t < 16; t++) score = fmaf(fmaxf(f1[t], 0.0f), sF2[t], score);

    out[(long long)b * (MC * MC) + i * MC + j] = score;
}

// ---------------- launch ----------------
extern "C" void kernel_launch(void* const* d_in, const int* in_sizes, int n_in,
                              void* d_out, int out_size) {
    (void)in_sizes; (void)n_in; (void)out_size;
    const float* seq    = (const float*)d_in[0];
    const float* logits = (const float*)d_in[1];
    const float* bboxes = (const float*)d_in[2];
    const int*   mask   = (const int*)  d_in[3];
    const float* Wk  = (const float*)d_in[4];
    const float* bk  = (const float*)d_in[5];
    const float* Wv  = (const float*)d_in[6];
    const float* bv  = (const float*)d_in[7];
    const float* Wbil= (const float*)d_in[8];
    const float* bbil= (const float*)d_in[9];
    const float* Ws1 = (const float*)d_in[10];
    const float* bs1 = (const float*)d_in[11];
    const float* Ws2 = (const float*)d_in[12];
    const float* bs2 = (const float*)d_in[13];
    const float* Wf1 = (const float*)d_in[14];
    const float* bf1 = (const float*)d_in[15];
    const float* Wf2 = (const float*)d_in[16];
    const float* bf2 = (const float*)d_in[17];
    float* out = (float*)d_out;

    // resolve device-global scratch addresses
    float *pWc, *pbc, *pvrep, *ptmp; int *pkidx, *pvidx;
    cudaGetSymbolAddress((void**)&pWc,  g_Wc);
    cudaGetSymbolAddress((void**)&pbc,  g_bc);
    cudaGetSymbolAddress((void**)&pvrep,g_valreps);
    cudaGetSymbolAddress((void**)&ptmp, g_tmp);
    cudaGetSymbolAddress((void**)&pkidx,g_kidx);
    cudaGetSymbolAddress((void**)&pvidx,g_vidx);

    conf_kernel<<<(BB * SS + 255) / 256, 256>>>(logits, mask);
    topk_kernel<<<dim3(BB, 2), 512>>>(bboxes, out);

    bc_kernel<<<HH / 128, 128>>>(bk, Wbil);

    // Wc = Wk @ Wbil   (768x768x768)
    sgemm128<<<dim3(HH / 128, HH / 128, 1), 256>>>(
        Wk, Wbil, nullptr, pWc, nullptr,
        Wk, Wbil, nullptr, pWc, nullptr);

    // z=0: val_reps = gather_v(seq) @ Wv + bv
    // z=1: tmp      = gather_k(seq) @ Wc + bc
    sgemm128<<<dim3(HH / 128, (BB * MC) / 128, 2), 256>>>(
        seq, Wv,  bv,  pvrep, pvidx,
        seq, pWc, pbc, ptmp,  pkidx);

    biaf_kernel<<<dim3(2, 2, BB), dim3(16, 16)>>>(bbil);

    pair_kernel<<<dim3(MC, BB), 128>>>(out, Ws1, bs1, Ws2, bs2, Wf1, bf1, Wf2, bf2);
}